// round 14
// baseline (speedup 1.0000x reference)
#include <cuda_runtime.h>
#include <cuda_bf16.h>
#include <cuda_fp8.h>
#include <cstdint>
#include <cstddef>

#define NT    9216
#define LCH   21
#define BB    2
#define NITERS 5
#define LROWS 24            // padded label rows; row 21 = ones (rowsum probe)
#define NBAND (NT / 32)     // 288 row-bands
#define KH    72            // k64 pairs per warp-set (NT/64/2)
#define PFA   4             // A prefetch depth
#define PFB   2             // B prefetch depth (L2-resident)

// ---------------- device scratch (no allocation allowed) ----------------
// +4KB pad: k_iter tail prefetch overruns by <256B (never consumed)
__device__ uint8_t g_Af8[(size_t)BB * NT * NT + 4096];
__device__ uint8_t g_Mf8[(size_t)BB * LROWS * NT + 4096];

// ---------------- helpers ----------------
__device__ __forceinline__ float ex2f(float x) {
    float y; asm("ex2.approx.f32 %0, %1;" : "=f"(y) : "f"(x)); return y;
}
__device__ __forceinline__ float fexp2(float y) {
    float r = y + 12582912.0f;
    float f = y - (r - 12582912.0f);
    int   n = __float_as_int(r);
    float s = __int_as_float((n + (127 - 0x4B400000)) << 23);
    float p = fmaf(0.00961813f, f, 0.05550411f);
    p = fmaf(p, f, 0.24022651f);
    p = fmaf(p, f, 0.69314718f);
    p = fmaf(p, f, 1.0f);
    return p * s;
}
__device__ __forceinline__ uint8_t to_fp8(float v) {
    return (uint8_t)__nv_cvt_float_to_fp8(v, __NV_SATFINITE, __NV_E4M3);
}

// ============================================================================
// Kernel 1: SYMMETRIC affinity (e4m3). Band i computes cols >= 32i only.
// Direct stores cover upper triangle + diagonal; mirrored rows (packed in
// registers via byte_perm) cover the strict lower triangle. Halves fma/MUFU.
// ============================================================================
__global__ __launch_bounds__(256) void k_affinity(const float* __restrict__ Refs) {
    __shared__ float4 rf[32];
    const int tid  = threadIdx.x;
    const int band = blockIdx.x % NBAND;
    const int b    = blockIdx.x / NBAND;
    const int n0   = band * 32;
    const float* F = Refs + (size_t)b * 3 * NT;

    if (tid < 32) {
        int n = n0 + tid;
        float x = F[n], y = F[NT + n], z = F[2 * NT + n];
        rf[tid] = make_float4(x, y, z, -0.72134752f * (x * x + y * y + z * z));
    }
    __syncthreads();

    const float4* Fx = (const float4*)F;
    const float4* Fy = (const float4*)(F + NT);
    const float4* Fz = (const float4*)(F + 2 * NT);
    uint8_t* Ab = g_Af8 + (size_t)b * NT * NT;

    for (int m4 = band * 8 + tid; m4 < NT / 4; m4 += 256) {
        float4 X = Fx[m4], Y = Fy[m4], Z = Fz[m4];
        float s0 = -0.72134752f * (X.x * X.x + Y.x * Y.x + Z.x * Z.x);
        float s1 = -0.72134752f * (X.y * X.y + Y.y * Y.y + Z.y * Z.y);
        float s2 = -0.72134752f * (X.z * X.z + Y.z * Y.z + Z.z * Z.z);
        float s3 = -0.72134752f * (X.w * X.w + Y.w * Y.w + Z.w * Z.w);

        uint32_t tr0[8], tr1[8], tr2[8], tr3[8];
        uint32_t a0 = 0, a1 = 0, a2 = 0, a3 = 0;
#pragma unroll
        for (int r = 0; r < 32; r++) {
            float4 f = rf[r];
            float e0 = ex2f(fmaf(X.x * f.x + Y.x * f.y + Z.x * f.z, 1.44269504f, f.w + s0));
            float e1 = ex2f(fmaf(X.y * f.x + Y.y * f.y + Z.y * f.z, 1.44269504f, f.w + s1));
            float e2 = ex2f(fmaf(X.z * f.x + Y.z * f.y + Z.z * f.z, 1.44269504f, f.w + s2));
            float e3 = ex2f(fmaf(X.w * f.x + Y.w * f.y + Z.w * f.z, 1.44269504f, f.w + s3));
            uint32_t lo = __nv_cvt_float2_to_fp8x2(make_float2(e0, e1),
                                                   __NV_SATFINITE, __NV_E4M3);
            uint32_t hi = __nv_cvt_float2_to_fp8x2(make_float2(e2, e3),
                                                   __NV_SATFINITE, __NV_E4M3);
            // direct store: row n0+r, cols 4*m4..4*m4+3
            ((uint32_t*)(Ab + (size_t)(n0 + r) * NT))[m4] = lo | (hi << 16);
            // transpose packing: byte r of mirrored rows 4*m4+c
            a0 = __byte_perm(a0, lo, 0x4321);
            a1 = __byte_perm(a1, lo, 0x5321);
            a2 = __byte_perm(a2, hi, 0x4321);
            a3 = __byte_perm(a3, hi, 0x5321);
            if ((r & 3) == 3) {
                tr0[r >> 2] = a0; tr1[r >> 2] = a1;
                tr2[r >> 2] = a2; tr3[r >> 2] = a3;
            }
        }
        // mirrored rows (strict lower triangle only; diagonal tile skipped)
        if (m4 >= band * 8 + 8) {
            const int m = m4 * 4;
            int4* t0 = (int4*)(Ab + (size_t)(m + 0) * NT + n0);
            int4* t1 = (int4*)(Ab + (size_t)(m + 1) * NT + n0);
            int4* t2 = (int4*)(Ab + (size_t)(m + 2) * NT + n0);
            int4* t3 = (int4*)(Ab + (size_t)(m + 3) * NT + n0);
            t0[0] = make_int4(tr0[0], tr0[1], tr0[2], tr0[3]);
            t0[1] = make_int4(tr0[4], tr0[5], tr0[6], tr0[7]);
            t1[0] = make_int4(tr1[0], tr1[1], tr1[2], tr1[3]);
            t1[1] = make_int4(tr1[4], tr1[5], tr1[6], tr1[7]);
            t2[0] = make_int4(tr2[0], tr2[1], tr2[2], tr2[3]);
            t2[1] = make_int4(tr2[4], tr2[5], tr2[6], tr2[7]);
            t3[0] = make_int4(tr3[0], tr3[1], tr3[2], tr3[3]);
            t3[1] = make_int4(tr3[4], tr3[5], tr3[6], tr3[7]);
        }
    }
}

// ============================================================================
// Kernel 2: initial softmax + Potts mix:  Mt = Mu @ softmax(-E0)  (e4m3)
// Row 21 = 1.0 (rowsum probe), rows 22/23 = 0.
// ============================================================================
__global__ __launch_bounds__(256) void k_softmax0(const float* __restrict__ E0,
                                                  const float* __restrict__ Mu) {
    __shared__ float mu[LCH * LCH];
    const int tid = threadIdx.x;
    for (int i = tid; i < LCH * LCH; i += 256) mu[i] = Mu[i];
    __syncthreads();

    const int pix = blockIdx.x * 256 + tid;
    const int b = pix / NT;
    const int n = pix - b * NT;
    const float* p = E0 + (size_t)b * LCH * NT + n;

    float v[LCH], mn = 3.4e38f;
#pragma unroll
    for (int l = 0; l < LCH; l++) { v[l] = p[(size_t)l * NT]; mn = fminf(mn, v[l]); }
    float s = 0.f;
#pragma unroll
    for (int l = 0; l < LCH; l++) { v[l] = fexp2(1.44269504f * (mn - v[l])); s += v[l]; }
    float is = 1.f / s;
#pragma unroll
    for (int l = 0; l < LCH; l++) v[l] *= is;

#pragma unroll
    for (int k = 0; k < LCH; k++) {
        float a = 0.f;
#pragma unroll
        for (int l = 0; l < LCH; l++) a = fmaf(mu[k * LCH + l], v[l], a);
        g_Mf8[((size_t)b * LROWS + k) * NT + n] = to_fp8(a);
    }
    g_Mf8[((size_t)b * LROWS + 21) * NT + n] = to_fp8(1.0f);  // rowsum probe
    g_Mf8[((size_t)b * LROWS + 22) * NT + n] = 0;
    g_Mf8[((size_t)b * LROWS + 23) * NT + n] = 0;
}

// ---------------- warp-level e4m3 MMA (sm_89+, no 'a' gating) ----------------
__device__ __forceinline__ void mma16832(float& c0, float& c1, float& c2, float& c3,
                                         uint32_t a0, uint32_t a1, uint32_t a2, uint32_t a3,
                                         uint32_t b0, uint32_t b1) {
    asm("mma.sync.aligned.m16n8k32.row.col.f32.e4m3.e4m3.f32 "
        "{%0,%1,%2,%3}, {%4,%5,%6,%7}, {%8,%9}, {%0,%1,%2,%3};"
        : "+f"(c0), "+f"(c1), "+f"(c2), "+f"(c3)
        : "r"(a0), "r"(a1), "r"(a2), "r"(a3), "r"(b0), "r"(b1));
}

// ============================================================================
// Kernel 3: one mean-field iteration via FP8 HMMA, K-split x2 in the CTA.
// R13 + unclamped prefetch (straight affine index; tail lands in array pad).
// ============================================================================
__global__ __launch_bounds__(512, 1) void k_iter(const float* __restrict__ E0,
                                                 const float* __restrict__ Mu,
                                                 float* __restrict__ out, int last) {
    __shared__ float Ds[2][128][25];
    __shared__ float mu_s[LCH * LCH];

    const int tid = threadIdx.x;
    const int wid = tid >> 5, lane = tid & 31;
    const int kset = wid >> 3, w8 = wid & 7;
    const int g = lane >> 2, q = lane & 3;
    const int b  = blockIdx.x / (NT / 128);
    const int nb = (blockIdx.x - b * (NT / 128)) * 128;

    for (int i = tid; i < LCH * LCH; i += 512) mu_s[i] = Mu[i];

    const int rowA = nb + 16 * w8 + g;
    const int ko = kset * KH * 4 + q;
    const int4* Ap0 = (const int4*)(g_Af8 + (size_t)(b * NT + rowA) * NT) + ko;
    const int4* Ap1 = (const int4*)(g_Af8 + (size_t)(b * NT + rowA + 8) * NT) + ko;
    const int4* Bp0 = (const int4*)(g_Mf8 + (size_t)(b * LROWS + g)      * NT) + ko;
    const int4* Bp1 = (const int4*)(g_Mf8 + (size_t)(b * LROWS + 8 + g)  * NT) + ko;
    const int4* Bp2 = (const int4*)(g_Mf8 + (size_t)(b * LROWS + 16 + g) * NT) + ko;

    float4 acc[3];
#pragma unroll
    for (int t = 0; t < 3; t++) acc[t] = make_float4(0.f, 0.f, 0.f, 0.f);

    int4 a0b[PFA], a1b[PFA];
    int4 b0b[PFB], b1b[PFB], b2b[PFB];
#pragma unroll
    for (int p = 0; p < PFA; p++) { a0b[p] = Ap0[p * 4]; a1b[p] = Ap1[p * 4]; }
#pragma unroll
    for (int p = 0; p < PFB; p++) { b0b[p] = Bp0[p * 4]; b1b[p] = Bp1[p * 4]; b2b[p] = Bp2[p * 4]; }

    for (int s0 = 0; s0 < KH; s0 += PFA) {
#pragma unroll
        for (int p = 0; p < PFA; p++) {
            const int s = s0 + p;
            const int pb = p & (PFB - 1);
            const uint32_t* A0 = (const uint32_t*)&a0b[p];
            const uint32_t* A1 = (const uint32_t*)&a1b[p];
            const uint32_t* B0 = (const uint32_t*)&b0b[pb];
            const uint32_t* B1 = (const uint32_t*)&b1b[pb];
            const uint32_t* B2 = (const uint32_t*)&b2b[pb];
            mma16832(acc[0].x, acc[0].y, acc[0].z, acc[0].w,
                     A0[0], A1[0], A0[1], A1[1], B0[0], B0[1]);
            mma16832(acc[1].x, acc[1].y, acc[1].z, acc[1].w,
                     A0[0], A1[0], A0[1], A1[1], B1[0], B1[1]);
            mma16832(acc[2].x, acc[2].y, acc[2].z, acc[2].w,
                     A0[0], A1[0], A0[1], A1[1], B2[0], B2[1]);
            mma16832(acc[0].x, acc[0].y, acc[0].z, acc[0].w,
                     A0[2], A1[2], A0[3], A1[3], B0[2], B0[3]);
            mma16832(acc[1].x, acc[1].y, acc[1].z, acc[1].w,
                     A0[2], A1[2], A0[3], A1[3], B1[2], B1[3]);
            mma16832(acc[2].x, acc[2].y, acc[2].z, acc[2].w,
                     A0[2], A1[2], A0[3], A1[3], B2[2], B2[3]);
            // unclamped affine-index prefetch (tail overrun lands in pad)
            a0b[p] = Ap0[(s + PFA) * 4]; a1b[p] = Ap1[(s + PFA) * 4];
            b0b[pb] = Bp0[(s + PFB) * 4]; b1b[pb] = Bp1[(s + PFB) * 4];
            b2b[pb] = Bp2[(s + PFB) * 4];
        }
    }

    const int r0 = 16 * w8 + g;
#pragma unroll
    for (int t = 0; t < 3; t++) {
        const int c = 8 * t + 2 * q;
        Ds[kset][r0][c]     = acc[t].x;  Ds[kset][r0][c + 1]     = acc[t].y;
        Ds[kset][r0 + 8][c] = acc[t].z;  Ds[kset][r0 + 8][c + 1] = acc[t].w;
    }
    __syncthreads();

    // ---- fused epilogue: inv from GEMM column 21 (rowsum of quantized A) ----
    if (tid < 128) {
        const int n = nb + tid;
        const float inv = 1.f / (Ds[0][tid][21] + Ds[1][tid][21]);
        const float* e0p = E0 + (size_t)b * LCH * NT + n;

        float pot[LCH], mn = 3.4e38f;
#pragma unroll
        for (int l = 0; l < LCH; l++) {
            float d = Ds[0][tid][l] + Ds[1][tid][l];
            pot[l] = e0p[(size_t)l * NT] + d * inv;
            mn = fminf(mn, pot[l]);
        }
        float s = 0.f;
#pragma unroll
        for (int l = 0; l < LCH; l++) { pot[l] = fexp2(1.44269504f * (mn - pot[l])); s += pot[l]; }
        float is = 1.f / s;
#pragma unroll
        for (int l = 0; l < LCH; l++) pot[l] *= is;

        if (last) {
            float* o = out + (size_t)b * LCH * NT + n;
#pragma unroll
            for (int l = 0; l < LCH; l++) o[(size_t)l * NT] = pot[l];
        } else {
#pragma unroll
            for (int k = 0; k < LCH; k++) {
                float a = 0.f;
#pragma unroll
                for (int l = 0; l < LCH; l++) a = fmaf(mu_s[k * LCH + l], pot[l], a);
                g_Mf8[((size_t)b * LROWS + k) * NT + n] = to_fp8(a);
            }
        }
    }
}

// ============================================================================
extern "C" void kernel_launch(void* const* d_in, const int* in_sizes, int n_in,
                              void* d_out, int out_size) {
    const float* E0   = (const float*)d_in[0];
    const float* Refs = (const float*)d_in[1];
    const float* Mu   = (const float*)d_in[2];
    float* out = (float*)d_out;

    k_affinity<<<BB * NBAND, 256>>>(Refs);
    k_softmax0<<<(BB * NT) / 256, 256>>>(E0, Mu);
    for (int it = 0; it < NITERS; it++)
        k_iter<<<BB * (NT / 128), 512>>>(E0, Mu, out, it == NITERS - 1);
}

// round 15
// speedup vs baseline: 1.1146x; 1.1146x over previous
#include <cuda_runtime.h>
#include <cuda_bf16.h>
#include <cuda_fp8.h>
#include <cstdint>
#include <cstddef>

#define NT    9216
#define LCH   21
#define BB    2
#define NITERS 5
#define LROWS 24            // padded label rows; row 21 = ones (rowsum probe)
#define NBAND (NT / 32)     // 288 row-bands
#define KH    72            // k64 pairs per warp-set (NT/64/2)
#define PFA   4             // A prefetch depth
#define PFB   2             // B prefetch depth (L2-resident)

// ---------------- device scratch (no allocation allowed) ----------------
__device__ uint8_t g_Af8[(size_t)BB * NT * NT];   // ~162 MB, e4m3, row-major [n][m]
__device__ uint8_t g_Mf8[(size_t)BB * LROWS * NT];// M^T e4m3: [b][l][m]

// ---------------- helpers ----------------
__device__ __forceinline__ float ex2f(float x) {
    float y; asm("ex2.approx.f32 %0, %1;" : "=f"(y) : "f"(x)); return y;
}
__device__ __forceinline__ float fexp2(float y) {
    float r = y + 12582912.0f;
    float f = y - (r - 12582912.0f);
    int   n = __float_as_int(r);
    float s = __int_as_float((n + (127 - 0x4B400000)) << 23);
    float p = fmaf(0.00961813f, f, 0.05550411f);
    p = fmaf(p, f, 0.24022651f);
    p = fmaf(p, f, 0.69314718f);
    p = fmaf(p, f, 1.0f);
    return p * s;
}
__device__ __forceinline__ uint8_t to_fp8(float v) {
    return (uint8_t)__nv_cvt_float_to_fp8(v, __NV_SATFINITE, __NV_E4M3);
}

// ============================================================================
// Kernel 1: SYMMETRIC affinity (e4m3), R14 version (measured ~2x faster).
// Band i computes cols >= 32i; direct stores = upper+diag, register-transposed
// mirror stores = strict lower. Halves fma-pipe and MUFU work.
// ============================================================================
__global__ __launch_bounds__(256) void k_affinity(const float* __restrict__ Refs) {
    __shared__ float4 rf[32];
    const int tid  = threadIdx.x;
    const int band = blockIdx.x % NBAND;
    const int b    = blockIdx.x / NBAND;
    const int n0   = band * 32;
    const float* F = Refs + (size_t)b * 3 * NT;

    if (tid < 32) {
        int n = n0 + tid;
        float x = F[n], y = F[NT + n], z = F[2 * NT + n];
        rf[tid] = make_float4(x, y, z, -0.72134752f * (x * x + y * y + z * z));
    }
    __syncthreads();

    const float4* Fx = (const float4*)F;
    const float4* Fy = (const float4*)(F + NT);
    const float4* Fz = (const float4*)(F + 2 * NT);
    uint8_t* Ab = g_Af8 + (size_t)b * NT * NT;

    for (int m4 = band * 8 + tid; m4 < NT / 4; m4 += 256) {
        float4 X = Fx[m4], Y = Fy[m4], Z = Fz[m4];
        float s0 = -0.72134752f * (X.x * X.x + Y.x * Y.x + Z.x * Z.x);
        float s1 = -0.72134752f * (X.y * X.y + Y.y * Y.y + Z.y * Z.y);
        float s2 = -0.72134752f * (X.z * X.z + Y.z * Y.z + Z.z * Z.z);
        float s3 = -0.72134752f * (X.w * X.w + Y.w * Y.w + Z.w * Z.w);

        uint32_t tr0[8], tr1[8], tr2[8], tr3[8];
        uint32_t a0 = 0, a1 = 0, a2 = 0, a3 = 0;
#pragma unroll
        for (int r = 0; r < 32; r++) {
            float4 f = rf[r];
            float e0 = ex2f(fmaf(X.x * f.x + Y.x * f.y + Z.x * f.z, 1.44269504f, f.w + s0));
            float e1 = ex2f(fmaf(X.y * f.x + Y.y * f.y + Z.y * f.z, 1.44269504f, f.w + s1));
            float e2 = ex2f(fmaf(X.z * f.x + Y.z * f.y + Z.z * f.z, 1.44269504f, f.w + s2));
            float e3 = ex2f(fmaf(X.w * f.x + Y.w * f.y + Z.w * f.z, 1.44269504f, f.w + s3));
            uint32_t lo = __nv_cvt_float2_to_fp8x2(make_float2(e0, e1),
                                                   __NV_SATFINITE, __NV_E4M3);
            uint32_t hi = __nv_cvt_float2_to_fp8x2(make_float2(e2, e3),
                                                   __NV_SATFINITE, __NV_E4M3);
            ((uint32_t*)(Ab + (size_t)(n0 + r) * NT))[m4] = lo | (hi << 16);
            a0 = __byte_perm(a0, lo, 0x4321);
            a1 = __byte_perm(a1, lo, 0x5321);
            a2 = __byte_perm(a2, hi, 0x4321);
            a3 = __byte_perm(a3, hi, 0x5321);
            if ((r & 3) == 3) {
                tr0[r >> 2] = a0; tr1[r >> 2] = a1;
                tr2[r >> 2] = a2; tr3[r >> 2] = a3;
            }
        }
        if (m4 >= band * 8 + 8) {
            const int m = m4 * 4;
            int4* t0 = (int4*)(Ab + (size_t)(m + 0) * NT + n0);
            int4* t1 = (int4*)(Ab + (size_t)(m + 1) * NT + n0);
            int4* t2 = (int4*)(Ab + (size_t)(m + 2) * NT + n0);
            int4* t3 = (int4*)(Ab + (size_t)(m + 3) * NT + n0);
            t0[0] = make_int4(tr0[0], tr0[1], tr0[2], tr0[3]);
            t0[1] = make_int4(tr0[4], tr0[5], tr0[6], tr0[7]);
            t1[0] = make_int4(tr1[0], tr1[1], tr1[2], tr1[3]);
            t1[1] = make_int4(tr1[4], tr1[5], tr1[6], tr1[7]);
            t2[0] = make_int4(tr2[0], tr2[1], tr2[2], tr2[3]);
            t2[1] = make_int4(tr2[4], tr2[5], tr2[6], tr2[7]);
            t3[0] = make_int4(tr3[0], tr3[1], tr3[2], tr3[3]);
            t3[1] = make_int4(tr3[4], tr3[5], tr3[6], tr3[7]);
        }
    }
}

// ============================================================================
// Kernel 2: initial softmax + Potts mix:  Mt = Mu @ softmax(-E0)  (e4m3)
// Row 21 = 1.0 (rowsum probe), rows 22/23 = 0.
// ============================================================================
__global__ __launch_bounds__(256) void k_softmax0(const float* __restrict__ E0,
                                                  const float* __restrict__ Mu) {
    __shared__ float mu[LCH * LCH];
    const int tid = threadIdx.x;
    for (int i = tid; i < LCH * LCH; i += 256) mu[i] = Mu[i];
    __syncthreads();

    const int pix = blockIdx.x * 256 + tid;
    const int b = pix / NT;
    const int n = pix - b * NT;
    const float* p = E0 + (size_t)b * LCH * NT + n;

    float v[LCH], mn = 3.4e38f;
#pragma unroll
    for (int l = 0; l < LCH; l++) { v[l] = p[(size_t)l * NT]; mn = fminf(mn, v[l]); }
    float s = 0.f;
#pragma unroll
    for (int l = 0; l < LCH; l++) { v[l] = fexp2(1.44269504f * (mn - v[l])); s += v[l]; }
    float is = 1.f / s;
#pragma unroll
    for (int l = 0; l < LCH; l++) v[l] *= is;

#pragma unroll
    for (int k = 0; k < LCH; k++) {
        float a = 0.f;
#pragma unroll
        for (int l = 0; l < LCH; l++) a = fmaf(mu[k * LCH + l], v[l], a);
        g_Mf8[((size_t)b * LROWS + k) * NT + n] = to_fp8(a);
    }
    g_Mf8[((size_t)b * LROWS + 21) * NT + n] = to_fp8(1.0f);  // rowsum probe
    g_Mf8[((size_t)b * LROWS + 22) * NT + n] = 0;
    g_Mf8[((size_t)b * LROWS + 23) * NT + n] = 0;
}

// ---------------- warp-level e4m3 MMA (sm_89+, no 'a' gating) ----------------
__device__ __forceinline__ void mma16832(float& c0, float& c1, float& c2, float& c3,
                                         uint32_t a0, uint32_t a1, uint32_t a2, uint32_t a3,
                                         uint32_t b0, uint32_t b1) {
    asm("mma.sync.aligned.m16n8k32.row.col.f32.e4m3.e4m3.f32 "
        "{%0,%1,%2,%3}, {%4,%5,%6,%7}, {%8,%9}, {%0,%1,%2,%3};"
        : "+f"(c0), "+f"(c1), "+f"(c2), "+f"(c3)
        : "r"(a0), "r"(a1), "r"(a2), "r"(a3), "r"(b0), "r"(b1));
}

// ============================================================================
// Kernel 3: FROZEN R13 k_iter (measured 42.4us) — clamped-index reloads
// (the form ptxas front-batches; R11/R14 alternatives both regressed).
// ============================================================================
__global__ __launch_bounds__(512, 1) void k_iter(const float* __restrict__ E0,
                                                 const float* __restrict__ Mu,
                                                 float* __restrict__ out, int last) {
    __shared__ float Ds[2][128][25];
    __shared__ float mu_s[LCH * LCH];

    const int tid = threadIdx.x;
    const int wid = tid >> 5, lane = tid & 31;
    const int kset = wid >> 3, w8 = wid & 7;
    const int g = lane >> 2, q = lane & 3;
    const int b  = blockIdx.x / (NT / 128);
    const int nb = (blockIdx.x - b * (NT / 128)) * 128;

    for (int i = tid; i < LCH * LCH; i += 512) mu_s[i] = Mu[i];

    const int rowA = nb + 16 * w8 + g;
    const int ko = kset * KH * 4 + q;
    const int4* Ap0 = (const int4*)(g_Af8 + (size_t)(b * NT + rowA) * NT) + ko;
    const int4* Ap1 = (const int4*)(g_Af8 + (size_t)(b * NT + rowA + 8) * NT) + ko;
    const int4* Bp0 = (const int4*)(g_Mf8 + (size_t)(b * LROWS + g)      * NT) + ko;
    const int4* Bp1 = (const int4*)(g_Mf8 + (size_t)(b * LROWS + 8 + g)  * NT) + ko;
    const int4* Bp2 = (const int4*)(g_Mf8 + (size_t)(b * LROWS + 16 + g) * NT) + ko;

    float4 acc[3];
#pragma unroll
    for (int t = 0; t < 3; t++) acc[t] = make_float4(0.f, 0.f, 0.f, 0.f);

    int4 a0b[PFA], a1b[PFA];
    int4 b0b[PFB], b1b[PFB], b2b[PFB];
#pragma unroll
    for (int p = 0; p < PFA; p++) { a0b[p] = Ap0[p * 4]; a1b[p] = Ap1[p * 4]; }
#pragma unroll
    for (int p = 0; p < PFB; p++) { b0b[p] = Bp0[p * 4]; b1b[p] = Bp1[p * 4]; b2b[p] = Bp2[p * 4]; }

    for (int s0 = 0; s0 < KH; s0 += PFA) {
#pragma unroll
        for (int p = 0; p < PFA; p++) {
            const int s = s0 + p;
            const int pb = p & (PFB - 1);
            const uint32_t* A0 = (const uint32_t*)&a0b[p];
            const uint32_t* A1 = (const uint32_t*)&a1b[p];
            const uint32_t* B0 = (const uint32_t*)&b0b[pb];
            const uint32_t* B1 = (const uint32_t*)&b1b[pb];
            const uint32_t* B2 = (const uint32_t*)&b2b[pb];
            mma16832(acc[0].x, acc[0].y, acc[0].z, acc[0].w,
                     A0[0], A1[0], A0[1], A1[1], B0[0], B0[1]);
            mma16832(acc[1].x, acc[1].y, acc[1].z, acc[1].w,
                     A0[0], A1[0], A0[1], A1[1], B1[0], B1[1]);
            mma16832(acc[2].x, acc[2].y, acc[2].z, acc[2].w,
                     A0[0], A1[0], A0[1], A1[1], B2[0], B2[1]);
            mma16832(acc[0].x, acc[0].y, acc[0].z, acc[0].w,
                     A0[2], A1[2], A0[3], A1[3], B0[2], B0[3]);
            mma16832(acc[1].x, acc[1].y, acc[1].z, acc[1].w,
                     A0[2], A1[2], A0[3], A1[3], B1[2], B1[3]);
            mma16832(acc[2].x, acc[2].y, acc[2].z, acc[2].w,
                     A0[2], A1[2], A0[3], A1[3], B2[2], B2[3]);
            // clamped-index reloads (compiler-batchable form — do not change)
            int an = s + PFA;
            int afx = (an < KH) ? an * 4 : 0;
            a0b[p] = Ap0[afx]; a1b[p] = Ap1[afx];
            int bn = s + PFB;
            int bfx = (bn < KH) ? bn * 4 : 0;
            b0b[pb] = Bp0[bfx]; b1b[pb] = Bp1[bfx]; b2b[pb] = Bp2[bfx];
        }
    }

    const int r0 = 16 * w8 + g;
#pragma unroll
    for (int t = 0; t < 3; t++) {
        const int c = 8 * t + 2 * q;
        Ds[kset][r0][c]     = acc[t].x;  Ds[kset][r0][c + 1]     = acc[t].y;
        Ds[kset][r0 + 8][c] = acc[t].z;  Ds[kset][r0 + 8][c + 1] = acc[t].w;
    }
    __syncthreads();

    // ---- fused epilogue: inv from GEMM column 21 (rowsum of quantized A) ----
    if (tid < 128) {
        const int n = nb + tid;
        const float inv = 1.f / (Ds[0][tid][21] + Ds[1][tid][21]);
        const float* e0p = E0 + (size_t)b * LCH * NT + n;

        float pot[LCH], mn = 3.4e38f;
#pragma unroll
        for (int l = 0; l < LCH; l++) {
            float d = Ds[0][tid][l] + Ds[1][tid][l];
            pot[l] = e0p[(size_t)l * NT] + d * inv;
            mn = fminf(mn, pot[l]);
        }
        float s = 0.f;
#pragma unroll
        for (int l = 0; l < LCH; l++) { pot[l] = fexp2(1.44269504f * (mn - pot[l])); s += pot[l]; }
        float is = 1.f / s;
#pragma unroll
        for (int l = 0; l < LCH; l++) pot[l] *= is;

        if (last) {
            float* o = out + (size_t)b * LCH * NT + n;
#pragma unroll
            for (int l = 0; l < LCH; l++) o[(size_t)l * NT] = pot[l];
        } else {
#pragma unroll
            for (int k = 0; k < LCH; k++) {
                float a = 0.f;
#pragma unroll
                for (int l = 0; l < LCH; l++) a = fmaf(mu_s[k * LCH + l], pot[l], a);
                g_Mf8[((size_t)b * LROWS + k) * NT + n] = to_fp8(a);
            }
        }
    }
}

// ============================================================================
extern "C" void kernel_launch(void* const* d_in, const int* in_sizes, int n_in,
                              void* d_out, int out_size) {
    const float* E0   = (const float*)d_in[0];
    const float* Refs = (const float*)d_in[1];
    const float* Mu   = (const float*)d_in[2];
    float* out = (float*)d_out;

    k_affinity<<<BB * NBAND, 256>>>(Refs);
    k_softmax0<<<(BB * NT) / 256, 256>>>(E0, Mu);
    for (int it = 0; it < NITERS; it++)
        k_iter<<<BB * (NT / 128), 512>>>(E0, Mu, out, it == NITERS - 1);
}